// round 10
// baseline (speedup 1.0000x reference)
#include <cuda_runtime.h>
#include <cuda_bf16.h>
#include <cstdint>

#define DIMV    64
#define KSPLIT  4
#define STAGES_PER_CTA 10     // 40 padded global stages / KSPLIT
#define RING    6
#define ROWSTRIDE 1088        // A row stride in smem (conflict-free LDS.128)
#define STAGE_BYTES (16 * ROWSTRIDE)   // 17408 (A only)
#define NKP 640                        // padded K-steps

// B packed as uint4, fragment order under the K-permutation that makes A loads
// float4-contiguous. ks in [625,640) explicitly zero-filled by pack_kernel.
__device__ uint4 g_Bp[NKP * 4 * 32];
__device__ float g_w[10240];     // per-row interaction scalar (memset each launch)
__device__ int   g_cnt[1024];    // per-tile split-K arrival counter (memset each launch)

// ---------------- helpers ----------------
__device__ __forceinline__ uint32_t cvt_bf16x2(float lo, float hi) {
    uint32_t r;
    asm("cvt.rn.bf16x2.f32 %0, %1, %2;" : "=r"(r) : "f"(hi), "f"(lo));
    return r;
}
__device__ __forceinline__ uint32_t smem_u32(const void* p) {
    uint32_t a;
    asm("{ .reg .u64 t; cvta.to.shared.u64 t, %1; cvt.u32.u64 %0, t; }" : "=r"(a) : "l"(p));
    return a;
}
__device__ __forceinline__ void cp_async16(uint32_t dst, const void* src) {
    asm volatile("cp.async.cg.shared.global [%0], [%1], 16;"
                 :: "r"(dst), "l"(src) : "memory");
}
#define CP_COMMIT() asm volatile("cp.async.commit_group;" ::: "memory")
#define CP_WAIT()   asm volatile("cp.async.wait_group %0;" :: "n"(RING - 2) : "memory")

__device__ __forceinline__ void lds128(float4& v, uint32_t addr) {
    asm volatile("ld.shared.v4.f32 {%0,%1,%2,%3}, [%4];"
                 : "=f"(v.x), "=f"(v.y), "=f"(v.z), "=f"(v.w) : "r"(addr));
}
__device__ __forceinline__ void mma16816(float c[4], const uint32_t a[4],
                                         uint32_t b0, uint32_t b1) {
    asm volatile(
        "mma.sync.aligned.m16n8k16.row.col.f32.bf16.bf16.f32 "
        "{%0,%1,%2,%3}, {%4,%5,%6,%7}, {%8,%9}, {%0,%1,%2,%3};"
        : "+f"(c[0]), "+f"(c[1]), "+f"(c[2]), "+f"(c[3])
        : "r"(a[0]), "r"(a[1]), "r"(a[2]), "r"(a[3]), "r"(b0), "r"(b1));
}

// ---------------- kernel 1: pack x -> Bp, 4 K-steps per block ----------------
// grid = NKP/4 = 160, block = 256. Rows >= N contribute zeros (K-pad).
__global__ void __launch_bounds__(256) pack_kernel(const float* __restrict__ x, int N) {
    __shared__ float xs[64][64];
    int rowbase = blockIdx.x * 64;
    for (int i = threadIdx.x; i < 64 * 64; i += 256) {
        int r = i >> 6, c = i & 63;
        int k = rowbase + r;
        xs[r][c] = (k < N) ? x[(size_t)k * DIMV + c] : 0.0f;
    }
    __syncthreads();
    int w = threadIdx.x >> 5, lane = threadIdx.x & 31;
    int g = lane >> 2, t = lane & 3;
#pragma unroll
    for (int p = 0; p < 2; p++) {
        int task = w + 8 * p;         // 0..15
        int ksl = task >> 2;          // local K-step 0..3
        int jj  = task & 3;
        int n0 = jj * 16 + g, n1 = n0 + 8;
        int rb = ksl * 16;
        uint4 v;
        v.x = cvt_bf16x2(xs[rb + 4 * t][n0],     xs[rb + 4 * t + 1][n0]);
        v.y = cvt_bf16x2(xs[rb + 4 * t + 2][n0], xs[rb + 4 * t + 3][n0]);
        v.z = cvt_bf16x2(xs[rb + 4 * t][n1],     xs[rb + 4 * t + 1][n1]);
        v.w = cvt_bf16x2(xs[rb + 4 * t + 2][n1], xs[rb + 4 * t + 3][n1]);
        int ks = blockIdx.x * 4 + ksl;
        g_Bp[(size_t)(ks * 4 + jj) * 32 + lane] = v;
    }
}

// ---------------- kernel 2: staged GEMM, split-K x4, fused finish ----------------
__global__ void __launch_bounds__(256, 2)
gemm_kernel(const float* __restrict__ A, const float* __restrict__ x,
            float* __restrict__ out, int N) {
    extern __shared__ char ring[];          // RING * STAGE_BYTES
    __shared__ float wred[8][16];
    __shared__ int lastflag;

    int tid = threadIdx.x, w = tid >> 5, lane = tid & 31;
    int g = lane >> 2, t = lane & 3;
    int tile  = blockIdx.x >> 2;
    int kpart = blockIdx.x & 3;
    int row0 = tile * 16;
    int sgbase = kpart * STAGES_PER_CTA;

    uint32_t sb = smem_u32(ring);
    int col16 = tid & 63;                   // A loader: 16B column slot
    int rbase = tid >> 6;                   // A loader: rows rbase + 4q

    float c[8][4];
#pragma unroll
    for (int j = 0; j < 8; j++)
#pragma unroll
        for (int q = 0; q < 4; q++) c[j][q] = 0.0f;

    // A stage loader (k clamped to row start for pad K-steps; B pad = 0)
    auto load_stage = [&](int ls) {
        int sg = sgbase + ls;
        int ri = ls;
        while (ri >= RING) ri -= RING;
        uint32_t base = sb + (uint32_t)ri * STAGE_BYTES;
        int gk = sg * 256 + col16 * 4;
        int gks = (gk < N) ? gk : 0;
        uint32_t da = base + col16 * 16;
#pragma unroll
        for (int q = 0; q < 4; q++) {
            int row = rbase + 4 * q;
            cp_async16(da + row * ROWSTRIDE, A + (size_t)(row0 + row) * N + gks);
        }
    };

#pragma unroll
    for (int ls = 0; ls < RING - 1; ls++) { load_stage(ls); CP_COMMIT(); }

    const uint4* pB = g_Bp + lane;
    int buf = 0;

    for (int ls = 0; ls < STAGES_PER_CTA; ls++) {
        int sg = sgbase + ls;
        CP_WAIT();
        __syncthreads();

        // B fragments from L2: warp w owns K-steps 2w, 2w+1 of this stage
        int ks0 = sg * 16 + 2 * w;
        uint4 b0[4], b1[4];
#pragma unroll
        for (int jj = 0; jj < 4; jj++) {
            b0[jj] = pB[(size_t)(ks0 * 4 + jj) * 32];
            b1[jj] = pB[(size_t)((ks0 + 1) * 4 + jj) * 32];
        }

        // A fragments from smem (conflict-free LDS.128)
        uint32_t abase = sb + (uint32_t)buf * STAGE_BYTES + g * ROWSTRIDE
                       + (2 * w) * 64 + t * 16;
        float4 va0, vb0, va1, vb1;
        lds128(va0, abase);
        lds128(vb0, abase + 8 * ROWSTRIDE);
        lds128(va1, abase + 64);
        lds128(vb1, abase + 64 + 8 * ROWSTRIDE);

        uint32_t ar0[4], ar1[4];
        ar0[0] = cvt_bf16x2(va0.x, va0.y);
        ar0[1] = cvt_bf16x2(vb0.x, vb0.y);
        ar0[2] = cvt_bf16x2(va0.z, va0.w);
        ar0[3] = cvt_bf16x2(vb0.z, vb0.w);
        ar1[0] = cvt_bf16x2(va1.x, va1.y);
        ar1[1] = cvt_bf16x2(vb1.x, vb1.y);
        ar1[2] = cvt_bf16x2(va1.z, va1.w);
        ar1[3] = cvt_bf16x2(vb1.z, vb1.w);

#pragma unroll
        for (int jj = 0; jj < 4; jj++) {
            mma16816(c[2 * jj],     ar0, b0[jj].x, b0[jj].y);
            mma16816(c[2 * jj + 1], ar0, b0[jj].z, b0[jj].w);
            mma16816(c[2 * jj],     ar1, b1[jj].x, b1[jj].y);
            mma16816(c[2 * jj + 1], ar1, b1[jj].z, b1[jj].w);
        }

        int lsn = ls + RING - 1;
        if (lsn < STAGES_PER_CTA) load_stage(lsn);
        CP_COMMIT();

        buf = (buf + 1 == RING) ? 0 : buf + 1;
    }

    // ---- epilogue: partial dot x . (Ax)_partial, cross-warp reduce ----
    int r0 = row0 + g, r1 = r0 + 8;
    float s0 = 0.0f, s1 = 0.0f;
#pragma unroll
    for (int j = 0; j < 8; j++) {
        int col = j * 8 + t * 2;
        float2 x0 = *(const float2*)(x + (size_t)r0 * DIMV + col);
        float2 x1 = *(const float2*)(x + (size_t)r1 * DIMV + col);
        s0 += x0.x * c[j][0] + x0.y * c[j][1];
        s1 += x1.x * c[j][2] + x1.y * c[j][3];
    }
    s0 += __shfl_xor_sync(0xFFFFFFFFu, s0, 1);
    s0 += __shfl_xor_sync(0xFFFFFFFFu, s0, 2);
    s1 += __shfl_xor_sync(0xFFFFFFFFu, s1, 1);
    s1 += __shfl_xor_sync(0xFFFFFFFFu, s1, 2);

    if (t == 0) { wred[w][g] = s0; wred[w][g + 8] = s1; }
    __syncthreads();

    if (tid < 16) {
        float acc = 0.0f;
#pragma unroll
        for (int q = 0; q < 8; q++) acc += wred[q][tid];
        atomicAdd(&g_w[row0 + tid], acc);
    }
    __syncthreads();
    if (tid == 0) {
        __threadfence();
        int old = atomicAdd(&g_cnt[tile], 1);
        lastflag = (old == KSPLIT - 1);
    }
    __syncthreads();

    // last-arriving CTA of this tile writes the final output tile
    if (lastflag) {
        int r = tid >> 4, cq = tid & 15;
        float inter = 0.01f * __ldcg(&g_w[row0 + r]);
        float4 xv = *(const float4*)(x + (size_t)(row0 + r) * DIMV + cq * 4);
        float4 o;
        o.x = 1.0f - 0.1f * xv.x - inter;
        o.y = 1.0f - 0.1f * xv.y - inter;
        o.z = 1.0f - 0.1f * xv.z - inter;
        o.w = 1.0f - 0.1f * xv.w - inter;
        *(float4*)(out + (size_t)(row0 + r) * DIMV + cq * 4) = o;
    }
}

// ---------------- launch ----------------
extern "C" void kernel_launch(void* const* d_in, const int* in_sizes, int n_in,
                              void* d_out, int out_size) {
    const float* x = (const float*)d_in[1];
    const float* A = (const float*)d_in[2];
    float* out = (float*)d_out;
    int N = in_sizes[1] / DIMV;   // 10000

    void* wptr = nullptr; void* cptr = nullptr;
    cudaGetSymbolAddress(&wptr, g_w);
    cudaGetSymbolAddress(&cptr, g_cnt);
    cudaMemsetAsync(wptr, 0, sizeof(float) * 10240);
    cudaMemsetAsync(cptr, 0, sizeof(int) * 1024);

    pack_kernel<<<NKP / 4, 256>>>(x, N);

    cudaFuncSetAttribute(gemm_kernel, cudaFuncAttributeMaxDynamicSharedMemorySize,
                         RING * STAGE_BYTES);
    gemm_kernel<<<(N / 16) * KSPLIT, 256, RING * STAGE_BYTES>>>(A, x, out, N);
}

// round 11
// speedup vs baseline: 1.0012x; 1.0012x over previous
#include <cuda_runtime.h>
#include <cuda_bf16.h>
#include <cstdint>

#define DIMV    64
#define KSPLIT  4
#define STAGES_PER_CTA 20     // 80 padded global stages / KSPLIT
#define RING    4
#define ROWS    32            // rows per CTA tile
#define ROWSTRIDE 544         // bytes per row in smem stage (512 data + 32 pad)
#define STAGE_BYTES (ROWS * ROWSTRIDE)  // 17408
#define NKP 640               // padded K-steps (8 per stage, 80 stages)

// B packed as uint4, fragment order under the K-permutation that makes A loads
// float4-contiguous. ks in [625,640) explicitly zero-filled by pack_kernel.
__device__ uint4 g_Bp[NKP * 4 * 32];
__device__ float g_w[10240];     // per-row interaction scalar (memset each launch)
__device__ int   g_cnt[1024];    // per-tile split-K arrival counter (memset each launch)

// ---------------- helpers ----------------
__device__ __forceinline__ uint32_t cvt_bf16x2(float lo, float hi) {
    uint32_t r;
    asm("cvt.rn.bf16x2.f32 %0, %1, %2;" : "=r"(r) : "f"(hi), "f"(lo));
    return r;
}
__device__ __forceinline__ uint32_t smem_u32(const void* p) {
    uint32_t a;
    asm("{ .reg .u64 t; cvta.to.shared.u64 t, %1; cvt.u32.u64 %0, t; }" : "=r"(a) : "l"(p));
    return a;
}
__device__ __forceinline__ void cp_async16(uint32_t dst, const void* src) {
    asm volatile("cp.async.cg.shared.global [%0], [%1], 16;"
                 :: "r"(dst), "l"(src) : "memory");
}
#define CP_COMMIT() asm volatile("cp.async.commit_group;" ::: "memory")
#define CP_WAIT()   asm volatile("cp.async.wait_group %0;" :: "n"(RING - 2) : "memory")

__device__ __forceinline__ void lds128(float4& v, uint32_t addr) {
    asm volatile("ld.shared.v4.f32 {%0,%1,%2,%3}, [%4];"
                 : "=f"(v.x), "=f"(v.y), "=f"(v.z), "=f"(v.w) : "r"(addr));
}
__device__ __forceinline__ void mma16816(float c[4], const uint32_t a[4],
                                         uint32_t b0, uint32_t b1) {
    asm volatile(
        "mma.sync.aligned.m16n8k16.row.col.f32.bf16.bf16.f32 "
        "{%0,%1,%2,%3}, {%4,%5,%6,%7}, {%8,%9}, {%0,%1,%2,%3};"
        : "+f"(c[0]), "+f"(c[1]), "+f"(c[2]), "+f"(c[3])
        : "r"(a[0]), "r"(a[1]), "r"(a[2]), "r"(a[3]), "r"(b0), "r"(b1));
}

// ---------------- kernel 1: pack x -> Bp, 4 K-steps per block ----------------
__global__ void __launch_bounds__(256) pack_kernel(const float* __restrict__ x, int N) {
    __shared__ float xs[64][64];
    int rowbase = blockIdx.x * 64;
    for (int i = threadIdx.x; i < 64 * 64; i += 256) {
        int r = i >> 6, c = i & 63;
        int k = rowbase + r;
        xs[r][c] = (k < N) ? x[(size_t)k * DIMV + c] : 0.0f;
    }
    __syncthreads();
    int w = threadIdx.x >> 5, lane = threadIdx.x & 31;
    int g = lane >> 2, t = lane & 3;
#pragma unroll
    for (int p = 0; p < 2; p++) {
        int task = w + 8 * p;         // 0..15
        int ksl = task >> 2;
        int jj  = task & 3;
        int n0 = jj * 16 + g, n1 = n0 + 8;
        int rb = ksl * 16;
        uint4 v;
        v.x = cvt_bf16x2(xs[rb + 4 * t][n0],     xs[rb + 4 * t + 1][n0]);
        v.y = cvt_bf16x2(xs[rb + 4 * t + 2][n0], xs[rb + 4 * t + 3][n0]);
        v.z = cvt_bf16x2(xs[rb + 4 * t][n1],     xs[rb + 4 * t + 1][n1]);
        v.w = cvt_bf16x2(xs[rb + 4 * t + 2][n1], xs[rb + 4 * t + 3][n1]);
        int ks = blockIdx.x * 4 + ksl;
        g_Bp[(size_t)(ks * 4 + jj) * 32 + lane] = v;
    }
}

// ---------------- kernel 2: 32-row staged GEMM, split-K x4, fused finish -----
__global__ void __launch_bounds__(256, 2)
gemm_kernel(const float* __restrict__ A, const float* __restrict__ x,
            float* __restrict__ out, int N) {
    extern __shared__ char ring[];          // RING * STAGE_BYTES
    __shared__ float wred[8][32];
    __shared__ int lastflag;

    int tid = threadIdx.x, w = tid >> 5, lane = tid & 31;
    int g = lane >> 2, t = lane & 3;
    int tile  = blockIdx.x >> 2;
    int kpart = blockIdx.x & 3;
    int row0 = tile * ROWS;
    int sgbase = kpart * STAGES_PER_CTA;

    uint32_t sb = smem_u32(ring);
    int col16 = tid & 31;                   // 16B column slot within row's 512B
    int rslot = tid >> 5;                   // rows rslot + 8q

    // accumulators: [row-subtile 0/1][j][quad]
    float c[2][8][4];
#pragma unroll
    for (int rt = 0; rt < 2; rt++)
#pragma unroll
        for (int j = 0; j < 8; j++)
#pragma unroll
            for (int q = 0; q < 4; q++) c[rt][j][q] = 0.0f;

    // A stage loader: 32 rows x 512 B (8 K-steps); clamp row & k for padding
    auto load_stage = [&](int ls) {
        int sg = sgbase + ls;
        uint32_t base = sb + (uint32_t)(ls & (RING - 1)) * STAGE_BYTES;
        int gk = sg * 128 + col16 * 4;
        int gks = (gk < N) ? gk : 0;        // pad K-steps have B == 0
        uint32_t da = base + col16 * 16;
#pragma unroll
        for (int q = 0; q < 4; q++) {
            int row = rslot + 8 * q;
            int grow = row0 + row; if (grow >= N) grow = N - 1;   // last-tile clamp
            cp_async16(da + row * ROWSTRIDE, A + (size_t)grow * N + gks);
        }
    };

#pragma unroll
    for (int ls = 0; ls < RING - 1; ls++) { load_stage(ls); CP_COMMIT(); }

    const uint4* pB = g_Bp + lane;

    for (int ls = 0; ls < STAGES_PER_CTA; ls++) {
        int sg = sgbase + ls;
        CP_WAIT();
        __syncthreads();

        // warp w owns K-step w of this stage
        int ks = sg * 8 + w;

        // B fragments (L2-resident); shared across both row subtiles
        uint4 bb[4];
#pragma unroll
        for (int jj = 0; jj < 4; jj++)
            bb[jj] = pB[(size_t)(ks * 4 + jj) * 32];

        // A fragments from smem: rows g, g+8 (subtile 0), g+16, g+24 (subtile 1)
        uint32_t abase = sb + (uint32_t)(ls & (RING - 1)) * STAGE_BYTES
                       + g * ROWSTRIDE + w * 64 + t * 16;
        float4 v0, v1, v2, v3;
        lds128(v0, abase);
        lds128(v1, abase + 8 * ROWSTRIDE);
        lds128(v2, abase + 16 * ROWSTRIDE);
        lds128(v3, abase + 24 * ROWSTRIDE);

        uint32_t ar0[4], ar1[4];
        ar0[0] = cvt_bf16x2(v0.x, v0.y);
        ar0[1] = cvt_bf16x2(v1.x, v1.y);
        ar0[2] = cvt_bf16x2(v0.z, v0.w);
        ar0[3] = cvt_bf16x2(v1.z, v1.w);
        ar1[0] = cvt_bf16x2(v2.x, v2.y);
        ar1[1] = cvt_bf16x2(v3.x, v3.y);
        ar1[2] = cvt_bf16x2(v2.z, v2.w);
        ar1[3] = cvt_bf16x2(v3.z, v3.w);

#pragma unroll
        for (int jj = 0; jj < 4; jj++) {
            mma16816(c[0][2 * jj],     ar0, bb[jj].x, bb[jj].y);
            mma16816(c[0][2 * jj + 1], ar0, bb[jj].z, bb[jj].w);
            mma16816(c[1][2 * jj],     ar1, bb[jj].x, bb[jj].y);
            mma16816(c[1][2 * jj + 1], ar1, bb[jj].z, bb[jj].w);
        }

        int lsn = ls + RING - 1;
        if (lsn < STAGES_PER_CTA) load_stage(lsn);
        CP_COMMIT();
    }

    // ---- epilogue: partial dot x . (Ax)_partial for 4 owned rows ----
#pragma unroll
    for (int rt = 0; rt < 2; rt++) {
        int r0 = row0 + rt * 16 + g;
        int r1 = r0 + 8;
        int r0c = (r0 < N) ? r0 : N - 1;
        int r1c = (r1 < N) ? r1 : N - 1;
        float s0 = 0.0f, s1 = 0.0f;
#pragma unroll
        for (int j = 0; j < 8; j++) {
            int col = j * 8 + t * 2;
            float2 x0 = *(const float2*)(x + (size_t)r0c * DIMV + col);
            float2 x1 = *(const float2*)(x + (size_t)r1c * DIMV + col);
            s0 += x0.x * c[rt][j][0] + x0.y * c[rt][j][1];
            s1 += x1.x * c[rt][j][2] + x1.y * c[rt][j][3];
        }
        s0 += __shfl_xor_sync(0xFFFFFFFFu, s0, 1);
        s0 += __shfl_xor_sync(0xFFFFFFFFu, s0, 2);
        s1 += __shfl_xor_sync(0xFFFFFFFFu, s1, 1);
        s1 += __shfl_xor_sync(0xFFFFFFFFu, s1, 2);
        if (t == 0) {
            wred[w][rt * 16 + g] = s0;
            wred[w][rt * 16 + g + 8] = s1;
        }
    }
    __syncthreads();

    if (tid < 32) {
        int grow = row0 + tid;
        if (grow < N) {
            float acc = 0.0f;
#pragma unroll
            for (int q = 0; q < 8; q++) acc += wred[q][tid];
            atomicAdd(&g_w[grow], acc);
        }
    }
    __syncthreads();
    if (tid == 0) {
        __threadfence();
        int old = atomicAdd(&g_cnt[tile], 1);
        lastflag = (old == KSPLIT - 1);
    }
    __syncthreads();

    // last-arriving CTA of this tile writes the final 32x64 output tile
    if (lastflag) {
#pragma unroll
        for (int p = 0; p < 2; p++) {
            int i = tid + p * 256;            // 512 float4s
            int r = i >> 4, cq = i & 15;
            int grow = row0 + r;
            if (grow < N) {
                float inter = 0.01f * __ldcg(&g_w[grow]);
                float4 xv = *(const float4*)(x + (size_t)grow * DIMV + cq * 4);
                float4 o;
                o.x = 1.0f - 0.1f * xv.x - inter;
                o.y = 1.0f - 0.1f * xv.y - inter;
                o.z = 1.0f - 0.1f * xv.z - inter;
                o.w = 1.0f - 0.1f * xv.w - inter;
                *(float4*)(out + (size_t)grow * DIMV + cq * 4) = o;
            }
        }
    }
}

// ---------------- launch ----------------
extern "C" void kernel_launch(void* const* d_in, const int* in_sizes, int n_in,
                              void* d_out, int out_size) {
    const float* x = (const float*)d_in[1];
    const float* A = (const float*)d_in[2];
    float* out = (float*)d_out;
    int N = in_sizes[1] / DIMV;   // 10000

    void* wptr = nullptr; void* cptr = nullptr;
    cudaGetSymbolAddress(&wptr, g_w);
    cudaGetSymbolAddress(&cptr, g_cnt);
    cudaMemsetAsync(wptr, 0, sizeof(float) * 10240);
    cudaMemsetAsync(cptr, 0, sizeof(int) * 1024);

    pack_kernel<<<NKP / 4, 256>>>(x, N);

    int ntiles = (N + ROWS - 1) / ROWS;      // 313
    cudaFuncSetAttribute(gemm_kernel, cudaFuncAttributeMaxDynamicSharedMemorySize,
                         RING * STAGE_BYTES);
    gemm_kernel<<<ntiles * KSPLIT, 256, RING * STAGE_BYTES>>>(A, x, out, N);
}

// round 12
// speedup vs baseline: 1.0471x; 1.0458x over previous
#include <cuda_runtime.h>
#include <cuda_bf16.h>
#include <cstdint>

#define DIMV    64
#define KSPLIT  4
#define STAGES_PER_CTA 10     // 40 padded global stages / KSPLIT
#define RING    4
#define ROWSTRIDE 1088        // A row stride in smem (conflict-free LDS.128)
#define STAGE_BYTES (16 * ROWSTRIDE)   // 17408
#define NKP 640               // padded K-steps

// B packed as uint4, fragment order under the K-permutation that makes A loads
// float4-contiguous. ks in [625,640) explicitly zero-filled by pack_kernel.
__device__ uint4 g_Bp[NKP * 4 * 32];
__device__ float g_w[10240];     // per-row interaction scalar (memset each launch)

// ---------------- helpers ----------------
__device__ __forceinline__ uint32_t cvt_bf16x2(float lo, float hi) {
    uint32_t r;
    asm("cvt.rn.bf16x2.f32 %0, %1, %2;" : "=r"(r) : "f"(hi), "f"(lo));
    return r;
}
__device__ __forceinline__ uint32_t smem_u32(const void* p) {
    uint32_t a;
    asm("{ .reg .u64 t; cvta.to.shared.u64 t, %1; cvt.u32.u64 %0, t; }" : "=r"(a) : "l"(p));
    return a;
}
#define MBAR_INIT(addr, cnt) \
    asm volatile("mbarrier.init.shared.b64 [%0], %1;" :: "r"(addr), "r"(cnt) : "memory")
#define MBAR_EXPECT_TX(addr, bytes) \
    asm volatile("mbarrier.arrive.expect_tx.shared.b64 _, [%0], %1;" \
                 :: "r"(addr), "r"(bytes) : "memory")
#define MBAR_WAIT(addr, par) do {                                              \
    uint32_t _m = (addr); uint32_t _p = (par); uint32_t _d;                    \
    asm volatile("{ .reg .pred p;"                                             \
        " mbarrier.try_wait.parity.acquire.cta.shared::cta.b64 p, [%1], %2;"   \
        " selp.b32 %0, 1, 0, p; }" : "=r"(_d) : "r"(_m), "r"(_p) : "memory");  \
    if (!_d) {                                                                 \
        asm volatile("{ .reg .pred P1;"                                        \
            "WL_%=:"                                                           \
            " mbarrier.try_wait.parity.acquire.cta.shared::cta.b64 P1, [%0], %1, 0x989680;" \
            " @P1 bra.uni WD_%=;"                                              \
            " bra.uni WL_%=;"                                                  \
            "WD_%=: }" :: "r"(_m), "r"(_p) : "memory");                        \
    }                                                                          \
} while (0)

__device__ __forceinline__ void bulk_cp(uint32_t dst, const void* src,
                                        uint32_t bytes, uint32_t mbar) {
    asm volatile(
        "cp.async.bulk.shared::cta.global.mbarrier::complete_tx::bytes [%0], [%1], %2, [%3];"
        :: "r"(dst), "l"(src), "r"(bytes), "r"(mbar) : "memory");
}

__device__ __forceinline__ void lds128(float4& v, uint32_t addr) {
    asm volatile("ld.shared.v4.f32 {%0,%1,%2,%3}, [%4];"
                 : "=f"(v.x), "=f"(v.y), "=f"(v.z), "=f"(v.w) : "r"(addr));
}
__device__ __forceinline__ void mma16816(float c[4], const uint32_t a[4],
                                         uint32_t b0, uint32_t b1) {
    asm volatile(
        "mma.sync.aligned.m16n8k16.row.col.f32.bf16.bf16.f32 "
        "{%0,%1,%2,%3}, {%4,%5,%6,%7}, {%8,%9}, {%0,%1,%2,%3};"
        : "+f"(c[0]), "+f"(c[1]), "+f"(c[2]), "+f"(c[3])
        : "r"(a[0]), "r"(a[1]), "r"(a[2]), "r"(a[3]), "r"(b0), "r"(b1));
}

// ---------------- kernel 1: pack x -> Bp, 4 K-steps per block ----------------
__global__ void __launch_bounds__(256) pack_kernel(const float* __restrict__ x, int N) {
    __shared__ float xs[64][64];
    int rowbase = blockIdx.x * 64;
    for (int i = threadIdx.x; i < 64 * 64; i += 256) {
        int r = i >> 6, c = i & 63;
        int k = rowbase + r;
        xs[r][c] = (k < N) ? x[(size_t)k * DIMV + c] : 0.0f;
    }
    __syncthreads();
    int w = threadIdx.x >> 5, lane = threadIdx.x & 31;
    int g = lane >> 2, t = lane & 3;
#pragma unroll
    for (int p = 0; p < 2; p++) {
        int task = w + 8 * p;
        int ksl = task >> 2;
        int jj  = task & 3;
        int n0 = jj * 16 + g, n1 = n0 + 8;
        int rb = ksl * 16;
        uint4 v;
        v.x = cvt_bf16x2(xs[rb + 4 * t][n0],     xs[rb + 4 * t + 1][n0]);
        v.y = cvt_bf16x2(xs[rb + 4 * t + 2][n0], xs[rb + 4 * t + 3][n0]);
        v.z = cvt_bf16x2(xs[rb + 4 * t][n1],     xs[rb + 4 * t + 1][n1]);
        v.w = cvt_bf16x2(xs[rb + 4 * t + 2][n1], xs[rb + 4 * t + 3][n1]);
        int ks = blockIdx.x * 4 + ksl;
        g_Bp[(size_t)(ks * 4 + jj) * 32 + lane] = v;
    }
}

// ---------------- kernel 2: staged GEMM via cp.async.bulk, split-K x4 --------
__global__ void __launch_bounds__(256, 2)
gemm_kernel(const float* __restrict__ A, const float* __restrict__ x, int N) {
    extern __shared__ char ring[];               // RING * STAGE_BYTES
    __shared__ alignas(8) uint64_t mbar[RING];
    __shared__ float wred[8][16];

    int tid = threadIdx.x, w = tid >> 5, lane = tid & 31;
    int g = lane >> 2, t = lane & 3;
    int tile  = blockIdx.x >> 2;
    int kpart = blockIdx.x & 3;
    int row0 = tile * 16;
    int sgbase = kpart * STAGES_PER_CTA;

    uint32_t sb = smem_u32(ring);
    uint32_t mb0 = smem_u32(&mbar[0]);

    if (tid == 0) {
#pragma unroll
        for (int s = 0; s < RING; s++) MBAR_INIT(mb0 + s * 8, 1);
    }
    __syncthreads();

    float c[8][4];
#pragma unroll
    for (int j = 0; j < 8; j++)
#pragma unroll
        for (int q = 0; q < 4; q++) c[j][q] = 0.0f;

    const char* Abase = (const char*)A;
    int rowbytes = N * 4;

    // producer: one thread issues 16 x 1KB bulk copies per stage
    auto produce = [&](int ls) {
        if (tid == 0) {
            int sg = sgbase + ls;
            int buf = ls & (RING - 1);
            int rem = rowbytes - sg * 1024;
            uint32_t sz = (rem >= 1024) ? 1024u : (uint32_t)rem;  // sg=39 -> 64
            uint32_t mba = mb0 + buf * 8;
            MBAR_EXPECT_TX(mba, 16u * sz);
            uint32_t dst = sb + (uint32_t)buf * STAGE_BYTES;
            const char* src = Abase + (size_t)row0 * rowbytes + (size_t)sg * 1024;
#pragma unroll
            for (int r = 0; r < 16; r++)
                bulk_cp(dst + r * ROWSTRIDE, src + (size_t)r * rowbytes, sz, mba);
        }
    };

#pragma unroll
    for (int ls = 0; ls < RING - 1; ls++) produce(ls);

    const uint4* pB = g_Bp + lane;
    int ph[RING] = {0, 0, 0, 0};

    for (int ls = 0; ls < STAGES_PER_CTA; ls++) {
        int sg = sgbase + ls;
        int buf = ls & (RING - 1);

        MBAR_WAIT(mb0 + buf * 8, ph[buf]);
        ph[buf] ^= 1;
        __syncthreads();

        // B fragments from L2: warp w owns K-steps 2w, 2w+1 of this stage
        int ks0 = sg * 16 + 2 * w;
        uint4 b0[4], b1[4];
#pragma unroll
        for (int jj = 0; jj < 4; jj++) {
            b0[jj] = pB[(size_t)(ks0 * 4 + jj) * 32];
            b1[jj] = pB[(size_t)((ks0 + 1) * 4 + jj) * 32];
        }

        // A fragments from smem (conflict-free LDS.128)
        uint32_t abase = sb + (uint32_t)buf * STAGE_BYTES + g * ROWSTRIDE
                       + (2 * w) * 64 + t * 16;
        float4 va0, vb0, va1, vb1;
        lds128(va0, abase);
        lds128(vb0, abase + 8 * ROWSTRIDE);
        lds128(va1, abase + 64);
        lds128(vb1, abase + 64 + 8 * ROWSTRIDE);

        uint32_t ar0[4], ar1[4];
        ar0[0] = cvt_bf16x2(va0.x, va0.y);
        ar0[1] = cvt_bf16x2(vb0.x, vb0.y);
        ar0[2] = cvt_bf16x2(va0.z, va0.w);
        ar0[3] = cvt_bf16x2(vb0.z, vb0.w);
        ar1[0] = cvt_bf16x2(va1.x, va1.y);
        ar1[1] = cvt_bf16x2(vb1.x, vb1.y);
        ar1[2] = cvt_bf16x2(va1.z, va1.w);
        ar1[3] = cvt_bf16x2(vb1.z, vb1.w);

#pragma unroll
        for (int jj = 0; jj < 4; jj++) {
            mma16816(c[2 * jj],     ar0, b0[jj].x, b0[jj].y);
            mma16816(c[2 * jj + 1], ar0, b0[jj].z, b0[jj].w);
            mma16816(c[2 * jj],     ar1, b1[jj].x, b1[jj].y);
            mma16816(c[2 * jj + 1], ar1, b1[jj].z, b1[jj].w);
        }

        int lsn = ls + RING - 1;
        if (lsn < STAGES_PER_CTA) produce(lsn);
    }

    // ---- epilogue: partial dot x . (Ax)_partial, cross-warp reduce ----
    int r0 = row0 + g, r1 = r0 + 8;
    float s0 = 0.0f, s1 = 0.0f;
#pragma unroll
    for (int j = 0; j < 8; j++) {
        int col = j * 8 + t * 2;
        float2 x0 = *(const float2*)(x + (size_t)r0 * DIMV + col);
        float2 x1 = *(const float2*)(x + (size_t)r1 * DIMV + col);
        s0 += x0.x * c[j][0] + x0.y * c[j][1];
        s1 += x1.x * c[j][2] + x1.y * c[j][3];
    }
    s0 += __shfl_xor_sync(0xFFFFFFFFu, s0, 1);
    s0 += __shfl_xor_sync(0xFFFFFFFFu, s0, 2);
    s1 += __shfl_xor_sync(0xFFFFFFFFu, s1, 1);
    s1 += __shfl_xor_sync(0xFFFFFFFFu, s1, 2);

    if (t == 0) { wred[w][g] = s0; wred[w][g + 8] = s1; }
    __syncthreads();

    if (tid < 16) {
        float acc = 0.0f;
#pragma unroll
        for (int q = 0; q < 8; q++) acc += wred[q][tid];
        atomicAdd(&g_w[row0 + tid], acc);
    }
}

// ---------------- kernel 3: elementwise finish ----------------
__global__ void __launch_bounds__(256) final_kernel(const float* __restrict__ x,
                                                    float* __restrict__ out) {
    int i = blockIdx.x * 256 + threadIdx.x;   // one float4 per thread
    int r = i >> 4, cq = i & 15;
    float inter = 0.01f * g_w[r];
    float4 xv = *(const float4*)(x + (size_t)r * DIMV + cq * 4);
    float4 o;
    o.x = 1.0f - 0.1f * xv.x - inter;
    o.y = 1.0f - 0.1f * xv.y - inter;
    o.z = 1.0f - 0.1f * xv.z - inter;
    o.w = 1.0f - 0.1f * xv.w - inter;
    *(float4*)(out + (size_t)r * DIMV + cq * 4) = o;
}

// ---------------- launch ----------------
extern "C" void kernel_launch(void* const* d_in, const int* in_sizes, int n_in,
                              void* d_out, int out_size) {
    const float* x = (const float*)d_in[1];
    const float* A = (const float*)d_in[2];
    float* out = (float*)d_out;
    int N = in_sizes[1] / DIMV;   // 10000

    void* wptr = nullptr;
    cudaGetSymbolAddress(&wptr, g_w);
    cudaMemsetAsync(wptr, 0, sizeof(float) * 10240);

    pack_kernel<<<NKP / 4, 256>>>(x, N);

    cudaFuncSetAttribute(gemm_kernel, cudaFuncAttributeMaxDynamicSharedMemorySize,
                         RING * STAGE_BYTES);
    gemm_kernel<<<(N / 16) * KSPLIT, 256, RING * STAGE_BYTES>>>(A, x, N);

    final_kernel<<<(N * DIMV) / (256 * 4), 256>>>(x, out);
}

// round 13
// speedup vs baseline: 1.2606x; 1.2039x over previous
#include <cuda_runtime.h>
#include <cuda_bf16.h>
#include <cstdint>

#define DIMV    64
#define KSPLIT  4
#define STAGES_PER_CTA 10     // 40 padded global stages / KSPLIT
#define RING    4
#define ROWSTRIDE 1088        // A row stride in smem (conflict-free LDS.128)
#define STAGE_BYTES (16 * ROWSTRIDE)   // 17408
#define NKP 640               // padded K-steps

// B packed as uint4, fragment order under the K-permutation that makes A loads
// float4-contiguous. ks in [625,640) zero-filled by pack_kernel each launch.
__device__ uint4 g_Bp[NKP * 4 * 32];
__device__ float g_w[10240];     // per-row interaction scalar (zeroed by pack_kernel)

// ---------------- helpers ----------------
__device__ __forceinline__ uint32_t cvt_bf16x2(float lo, float hi) {
    uint32_t r;
    asm("cvt.rn.bf16x2.f32 %0, %1, %2;" : "=r"(r) : "f"(hi), "f"(lo));
    return r;
}
__device__ __forceinline__ uint32_t smem_u32(const void* p) {
    uint32_t a;
    asm("{ .reg .u64 t; cvta.to.shared.u64 t, %1; cvt.u32.u64 %0, t; }" : "=r"(a) : "l"(p));
    return a;
}
__device__ __forceinline__ void cp_async16(uint32_t dst, const void* src) {
    asm volatile("cp.async.cg.shared.global [%0], [%1], 16;"
                 :: "r"(dst), "l"(src) : "memory");
}
#define CP_COMMIT() asm volatile("cp.async.commit_group;" ::: "memory")
#define CP_WAIT()   asm volatile("cp.async.wait_group %0;" :: "n"(RING - 2) : "memory")

__device__ __forceinline__ void lds128(float4& v, uint32_t addr) {
    asm volatile("ld.shared.v4.f32 {%0,%1,%2,%3}, [%4];"
                 : "=f"(v.x), "=f"(v.y), "=f"(v.z), "=f"(v.w) : "r"(addr));
}
__device__ __forceinline__ void mma16816(float c[4], const uint32_t a[4],
                                         uint32_t b0, uint32_t b1) {
    asm volatile(
        "mma.sync.aligned.m16n8k16.row.col.f32.bf16.bf16.f32 "
        "{%0,%1,%2,%3}, {%4,%5,%6,%7}, {%8,%9}, {%0,%1,%2,%3};"
        : "+f"(c[0]), "+f"(c[1]), "+f"(c[2]), "+f"(c[3])
        : "r"(a[0]), "r"(a[1]), "r"(a[2]), "r"(a[3]), "r"(b0), "r"(b1));
}

// ---------------- kernel 1: pack x -> Bp (smem-free, 1 warp per task) --------
// warpid = ks*4 + jj ; 2560 warps = 320 blocks x 8 warps.
// ks in [625,640) writes zeros. Blocks 0..39 also zero g_w (40*256 = 10240).
__global__ void __launch_bounds__(256) pack_kernel(const float* __restrict__ x, int N) {
    if (blockIdx.x < 40) g_w[blockIdx.x * 256 + threadIdx.x] = 0.0f;

    int warpid = blockIdx.x * 8 + (threadIdx.x >> 5);
    int lane = threadIdx.x & 31;
    int ks = warpid >> 2, jj = warpid & 3;
    if (ks >= NKP) return;

    int g = lane >> 2, t = lane & 3;
    int n0 = jj * 16 + g, n1 = n0 + 8;
    int k0 = ks * 16 + 4 * t;

    uint4 v = make_uint4(0u, 0u, 0u, 0u);
    if (ks * 16 < N) {   // full K-steps only (N % 16 == 0); pad stays zero
        const float* p0 = x + (size_t)k0 * DIMV;
        float a0 = __ldg(p0 + n0),            a1 = __ldg(p0 + DIMV + n0);
        float a2 = __ldg(p0 + 2 * DIMV + n0), a3 = __ldg(p0 + 3 * DIMV + n0);
        float b0 = __ldg(p0 + n1),            b1 = __ldg(p0 + DIMV + n1);
        float b2 = __ldg(p0 + 2 * DIMV + n1), b3 = __ldg(p0 + 3 * DIMV + n1);
        v.x = cvt_bf16x2(a0, a1);
        v.y = cvt_bf16x2(a2, a3);
        v.z = cvt_bf16x2(b0, b1);
        v.w = cvt_bf16x2(b2, b3);
    }
    g_Bp[(size_t)(ks * 4 + jj) * 32 + lane] = v;
}

// ---------------- kernel 2: staged GEMM, split-K x4 (R8 body, verbatim) ------
__global__ void __launch_bounds__(256, 2)
gemm_kernel(const float* __restrict__ A, const float* __restrict__ x, int N) {
    extern __shared__ char ring[];          // RING * STAGE_BYTES
    __shared__ float wred[8][16];

    int tid = threadIdx.x, w = tid >> 5, lane = tid & 31;
    int g = lane >> 2, t = lane & 3;
    int tile  = blockIdx.x >> 2;
    int kpart = blockIdx.x & 3;
    int row0 = tile * 16;
    int sgbase = kpart * STAGES_PER_CTA;

    uint32_t sb = smem_u32(ring);
    int col16 = tid & 63;                   // A loader: 16B column slot
    int rbase = tid >> 6;                   // A loader: rows rbase + 4q

    float c[8][4];
#pragma unroll
    for (int j = 0; j < 8; j++)
#pragma unroll
        for (int q = 0; q < 4; q++) c[j][q] = 0.0f;

    // A stage loader (k clamped to row start for pad K-steps; B pad = 0)
    auto load_stage = [&](int ls) {
        int sg = sgbase + ls;
        uint32_t base = sb + (uint32_t)(ls & (RING - 1)) * STAGE_BYTES;
        int gk = sg * 256 + col16 * 4;
        int gks = (gk < N) ? gk : 0;
        uint32_t da = base + col16 * 16;
#pragma unroll
        for (int q = 0; q < 4; q++) {
            int row = rbase + 4 * q;
            cp_async16(da + row * ROWSTRIDE, A + (size_t)(row0 + row) * N + gks);
        }
    };

#pragma unroll
    for (int ls = 0; ls < RING - 1; ls++) { load_stage(ls); CP_COMMIT(); }

    const uint4* pB = g_Bp + lane;

    for (int ls = 0; ls < STAGES_PER_CTA; ls++) {
        int sg = sgbase + ls;
        int buf = ls & (RING - 1);
        CP_WAIT();
        __syncthreads();

        // B fragments from L2: warp w owns K-steps 2w, 2w+1 of this stage
        int ks0 = sg * 16 + 2 * w;
        uint4 b0[4], b1[4];
#pragma unroll
        for (int jj = 0; jj < 4; jj++) {
            b0[jj] = pB[(size_t)(ks0 * 4 + jj) * 32];
            b1[jj] = pB[(size_t)((ks0 + 1) * 4 + jj) * 32];
        }

        // A fragments from smem (conflict-free LDS.128)
        uint32_t abase = sb + (uint32_t)buf * STAGE_BYTES + g * ROWSTRIDE
                       + (2 * w) * 64 + t * 16;
        float4 va0, vb0, va1, vb1;
        lds128(va0, abase);
        lds128(vb0, abase + 8 * ROWSTRIDE);
        lds128(va1, abase + 64);
        lds128(vb1, abase + 64 + 8 * ROWSTRIDE);

        uint32_t ar0[4], ar1[4];
        ar0[0] = cvt_bf16x2(va0.x, va0.y);
        ar0[1] = cvt_bf16x2(vb0.x, vb0.y);
        ar0[2] = cvt_bf16x2(va0.z, va0.w);
        ar0[3] = cvt_bf16x2(vb0.z, vb0.w);
        ar1[0] = cvt_bf16x2(va1.x, va1.y);
        ar1[1] = cvt_bf16x2(vb1.x, vb1.y);
        ar1[2] = cvt_bf16x2(va1.z, va1.w);
        ar1[3] = cvt_bf16x2(vb1.z, vb1.w);

#pragma unroll
        for (int jj = 0; jj < 4; jj++) {
            mma16816(c[2 * jj],     ar0, b0[jj].x, b0[jj].y);
            mma16816(c[2 * jj + 1], ar0, b0[jj].z, b0[jj].w);
            mma16816(c[2 * jj],     ar1, b1[jj].x, b1[jj].y);
            mma16816(c[2 * jj + 1], ar1, b1[jj].z, b1[jj].w);
        }

        int lsn = ls + RING - 1;
        if (lsn < STAGES_PER_CTA) load_stage(lsn);
        CP_COMMIT();
    }

    // ---- epilogue: partial dot x . (Ax)_partial, cross-warp reduce ----
    int r0 = row0 + g, r1 = r0 + 8;
    float s0 = 0.0f, s1 = 0.0f;
#pragma unroll
    for (int j = 0; j < 8; j++) {
        int col = j * 8 + t * 2;
        float2 x0 = *(const float2*)(x + (size_t)r0 * DIMV + col);
        float2 x1 = *(const float2*)(x + (size_t)r1 * DIMV + col);
        s0 += x0.x * c[j][0] + x0.y * c[j][1];
        s1 += x1.x * c[j][2] + x1.y * c[j][3];
    }
    s0 += __shfl_xor_sync(0xFFFFFFFFu, s0, 1);
    s0 += __shfl_xor_sync(0xFFFFFFFFu, s0, 2);
    s1 += __shfl_xor_sync(0xFFFFFFFFu, s1, 1);
    s1 += __shfl_xor_sync(0xFFFFFFFFu, s1, 2);

    if (t == 0) { wred[w][g] = s0; wred[w][g + 8] = s1; }
    __syncthreads();

    if (tid < 16) {
        float acc = 0.0f;
#pragma unroll
        for (int q = 0; q < 8; q++) acc += wred[q][tid];
        atomicAdd(&g_w[row0 + tid], acc);
    }
}

// ---------------- kernel 3: elementwise finish ----------------
__global__ void __launch_bounds__(256) final_kernel(const float* __restrict__ x,
                                                    float* __restrict__ out) {
    int i = blockIdx.x * 256 + threadIdx.x;   // one float4 per thread
    int r = i >> 4, cq = i & 15;
    float inter = 0.01f * g_w[r];
    float4 xv = *(const float4*)(x + (size_t)r * DIMV + cq * 4);
    float4 o;
    o.x = 1.0f - 0.1f * xv.x - inter;
    o.y = 1.0f - 0.1f * xv.y - inter;
    o.z = 1.0f - 0.1f * xv.z - inter;
    o.w = 1.0f - 0.1f * xv.w - inter;
    *(float4*)(out + (size_t)r * DIMV + cq * 4) = o;
}

// ---------------- launch ----------------
extern "C" void kernel_launch(void* const* d_in, const int* in_sizes, int n_in,
                              void* d_out, int out_size) {
    const float* x = (const float*)d_in[1];
    const float* A = (const float*)d_in[2];
    float* out = (float*)d_out;
    int N = in_sizes[1] / DIMV;   // 10000

    pack_kernel<<<320, 256>>>(x, N);   // also zeroes g_w

    cudaFuncSetAttribute(gemm_kernel, cudaFuncAttributeMaxDynamicSharedMemorySize,
                         RING * STAGE_BYTES);
    gemm_kernel<<<(N / 16) * KSPLIT, 256, RING * STAGE_BYTES>>>(A, x, N);

    final_kernel<<<(N * DIMV) / (256 * 4), 256>>>(x, out);
}

// round 14
// speedup vs baseline: 1.2724x; 1.0093x over previous
#include <cuda_runtime.h>
#include <cuda_bf16.h>
#include <cstdint>

#define DIMV    64
#define KSPLIT  4
#define KS_PER_CTA 160        // 640 padded K-steps / KSPLIT
#define NKP 640

// B packed as uint4, fragment order under the K-permutation that makes A loads
// float4-contiguous. ks in [625,640) zero-filled by pack_kernel each launch.
__device__ uint4 g_Bp[NKP * 4 * 32];
__device__ float g_w[10240];     // per-row interaction scalar (zeroed by pack_kernel)

// ---------------- helpers ----------------
__device__ __forceinline__ uint32_t cvt_bf16x2(float lo, float hi) {
    uint32_t r;
    asm("cvt.rn.bf16x2.f32 %0, %1, %2;" : "=r"(r) : "f"(hi), "f"(lo));
    return r;
}
__device__ __forceinline__ void mma16816(float c[4], const uint32_t a[4],
                                         uint32_t b0, uint32_t b1) {
    asm volatile(
        "mma.sync.aligned.m16n8k16.row.col.f32.bf16.bf16.f32 "
        "{%0,%1,%2,%3}, {%4,%5,%6,%7}, {%8,%9}, {%0,%1,%2,%3};"
        : "+f"(c[0]), "+f"(c[1]), "+f"(c[2]), "+f"(c[3])
        : "r"(a[0]), "r"(a[1]), "r"(a[2]), "r"(a[3]), "r"(b0), "r"(b1));
}

// ---------------- kernel 1: pack x -> Bp (smem-free, 1 warp per task) --------
// warpid = ks*4 + jj ; 2560 warps = 320 blocks x 8 warps.
// ks in [625,640) writes zeros. Blocks 0..39 also zero g_w (40*256 = 10240).
__global__ void __launch_bounds__(256) pack_kernel(const float* __restrict__ x, int N) {
    if (blockIdx.x < 40) g_w[blockIdx.x * 256 + threadIdx.x] = 0.0f;

    int warpid = blockIdx.x * 8 + (threadIdx.x >> 5);
    int lane = threadIdx.x & 31;
    int ks = warpid >> 2, jj = warpid & 3;
    if (ks >= NKP) return;

    int g = lane >> 2, t = lane & 3;
    int n0 = jj * 16 + g, n1 = n0 + 8;
    int k0 = ks * 16 + 4 * t;

    uint4 v = make_uint4(0u, 0u, 0u, 0u);
    if (ks * 16 < N) {
        const float* p0 = x + (size_t)k0 * DIMV;
        float a0 = __ldg(p0 + n0),            a1 = __ldg(p0 + DIMV + n0);
        float a2 = __ldg(p0 + 2 * DIMV + n0), a3 = __ldg(p0 + 3 * DIMV + n0);
        float b0 = __ldg(p0 + n1),            b1 = __ldg(p0 + DIMV + n1);
        float b2 = __ldg(p0 + 2 * DIMV + n1), b3 = __ldg(p0 + 3 * DIMV + n1);
        v.x = cvt_bf16x2(a0, a1);
        v.y = cvt_bf16x2(a2, a3);
        v.z = cvt_bf16x2(b0, b1);
        v.w = cvt_bf16x2(b2, b3);
    }
    g_Bp[(size_t)(ks * 4 + jj) * 32 + lane] = v;
}

// ---------------- kernel 2: direct-LDG GEMM, split-K x4 ----------------
// CTA = (tile 16 rows, kpart). 8 warps stride the CTA's 160 K-steps.
__global__ void __launch_bounds__(256, 2)
gemm_kernel(const float* __restrict__ A, const float* __restrict__ x, int N) {
    __shared__ float wred[8][16];

    int tid = threadIdx.x, w = tid >> 5, lane = tid & 31;
    int g = lane >> 2, t = lane & 3;
    int tile  = blockIdx.x >> 2;
    int kpart = blockIdx.x & 3;
    int row0 = tile * 16;
    int r0 = row0 + g, r1 = r0 + 8;

    const float* rowA0 = A + (size_t)r0 * N + 4 * t;
    const float* rowA1 = A + (size_t)r1 * N + 4 * t;
    const uint4* pB = g_Bp + lane;

    float c[8][4];
#pragma unroll
    for (int j = 0; j < 8; j++)
#pragma unroll
        for (int q = 0; q < 4; q++) c[j][q] = 0.0f;

    int ksbase = kpart * KS_PER_CTA + w;

#pragma unroll 4
    for (int i = 0; i < KS_PER_CTA / 8; i++) {     // 20 iterations
        int ks = ksbase + 8 * i;
        int gk = ks * 16;
        if (gk >= N) gk = 0;                        // pad K-step: B == 0

        float4 va = *(const float4*)(rowA0 + gk);
        float4 vb = *(const float4*)(rowA1 + gk);

        uint4 bb[4];
#pragma unroll
        for (int jj = 0; jj < 4; jj++)
            bb[jj] = pB[(size_t)(ks * 4 + jj) * 32];

        uint32_t ar[4];
        ar[0] = cvt_bf16x2(va.x, va.y);
        ar[1] = cvt_bf16x2(vb.x, vb.y);
        ar[2] = cvt_bf16x2(va.z, va.w);
        ar[3] = cvt_bf16x2(vb.z, vb.w);

#pragma unroll
        for (int jj = 0; jj < 4; jj++) {
            mma16816(c[2 * jj],     ar, bb[jj].x, bb[jj].y);
            mma16816(c[2 * jj + 1], ar, bb[jj].z, bb[jj].w);
        }
    }

    // ---- epilogue: partial dot x . (Ax)_partial, cross-warp reduce ----
    float s0 = 0.0f, s1 = 0.0f;
#pragma unroll
    for (int j = 0; j < 8; j++) {
        int col = j * 8 + t * 2;
        float2 x0 = *(const float2*)(x + (size_t)r0 * DIMV + col);
        float2 x1 = *(const float2*)(x + (size_t)r1 * DIMV + col);
        s0 += x0.x * c[j][0] + x0.y * c[j][1];
        s1 += x1.x * c[j][2] + x1.y * c[j][3];
    }
    s0 += __shfl_xor_sync(0xFFFFFFFFu, s0, 1);
    s0 += __shfl_xor_sync(0xFFFFFFFFu, s0, 2);
    s1 += __shfl_xor_sync(0xFFFFFFFFu, s1, 1);
    s1 += __shfl_xor_sync(0xFFFFFFFFu, s1, 2);

    if (t == 0) { wred[w][g] = s0; wred[w][g + 8] = s1; }
    __syncthreads();

    if (tid < 16) {
        float acc = 0.0f;
#pragma unroll
        for (int q = 0; q < 8; q++) acc += wred[q][tid];
        atomicAdd(&g_w[row0 + tid], acc);
    }
}

// ---------------- kernel 3: elementwise finish ----------------
__global__ void __launch_bounds__(256) final_kernel(const float* __restrict__ x,
                                                    float* __restrict__ out) {
    int i = blockIdx.x * 256 + threadIdx.x;   // one float4 per thread
    int r = i >> 4, cq = i & 15;
    float inter = 0.01f * g_w[r];
    float4 xv = *(const float4*)(x + (size_t)r * DIMV + cq * 4);
    float4 o;
    o.x = 1.0f - 0.1f * xv.x - inter;
    o.y = 1.0f - 0.1f * xv.y - inter;
    o.z = 1.0f - 0.1f * xv.z - inter;
    o.w = 1.0f - 0.1f * xv.w - inter;
    *(float4*)(out + (size_t)r * DIMV + cq * 4) = o;
}

// ---------------- launch ----------------
extern "C" void kernel_launch(void* const* d_in, const int* in_sizes, int n_in,
                              void* d_out, int out_size) {
    const float* x = (const float*)d_in[1];
    const float* A = (const float*)d_in[2];
    float* out = (float*)d_out;
    int N = in_sizes[1] / DIMV;   // 10000

    pack_kernel<<<320, 256>>>(x, N);   // also zeroes g_w

    gemm_kernel<<<(N / 16) * KSPLIT, 256>>>(A, x, N);

    final_kernel<<<(N * DIMV) / (256 * 4), 256>>>(x, out);
}